// round 8
// baseline (speedup 1.0000x reference)
#include <cuda_runtime.h>
#include <cuda_fp16.h>

#define HH 60
#define WW 60
#define DDZ 36
#define NP 2048
#define NC 13
#define GRID_SZ 0.08f

#define TXC 4
#define TYC 8
#define TZC 8
#define ROWS 256          // voxels per tile
#define TPB 128           // each thread owns rows t and t+128 (x-pair)
#define KB 16             // survivors per MMA batch
#define WPAD 264          // s_W row length in halves -> 528B stride (16B aligned, LDSM conflict-free)

// Per-Gaussian precomputed scratch (device globals: no allocation allowed)
__device__ int4   g_box[NP];        // bx, by, bz, r
__device__ float4 g_q0[NP];         // -0.5*ixx, -0.5*iyy, -0.5*izz, pad
__device__ float4 g_q1[NP];         // -ixy, -iyz, -ixz, mx
__device__ float2 g_q2[NP];         // my, mz
__device__ uint4  g_semh[NP][2];    // opacity*semantics as 16 fp16 (13 used, 3 zero)

__global__ void precompute_kernel(const float* __restrict__ means3D,
                                  const float* __restrict__ opac,
                                  const float* __restrict__ semantics,
                                  const float* __restrict__ scales,
                                  const float* __restrict__ cov3D,
                                  const float* __restrict__ origin)
{
    int g = blockIdx.x * blockDim.x + threadIdx.x;
    if (g >= NP) return;

    const float* cv = cov3D + g * 9;
    float a = cv[0], b = cv[4], c = cv[8];
    float d = cv[1], e = cv[5], f = cv[2];
    float det = a * (b * c - e * e) - d * (d * c - e * f) + f * (d * e - b * f);
    float ixx = (b * c - e * e) / det;
    float iyy = (a * c - f * f) / det;
    float izz = (a * b - d * d) / det;
    float ixy = (e * f - d * c) / det;
    float iyz = (d * f - a * e) / det;
    float ixz = (d * e - b * f) / det;

    float ox = origin[0], oy = origin[1], oz = origin[2];
    float mx = means3D[g * 3 + 0];
    float my = means3D[g * 3 + 1];
    float mz = means3D[g * 3 + 2];

    float s = fmaxf(scales[g * 3 + 0], fmaxf(scales[g * 3 + 1], scales[g * 3 + 2]));
    int r = (int)ceilf(s * 3.0f / GRID_SZ);

    g_box[g] = make_int4((int)((mx - ox) / GRID_SZ),
                         (int)((my - oy) / GRID_SZ),
                         (int)((mz - oz) / GRID_SZ), r);
    g_q0[g] = make_float4(-0.5f * ixx, -0.5f * iyy, -0.5f * izz, 0.0f);
    g_q1[g] = make_float4(-ixy, -iyz, -ixz, mx);
    g_q2[g] = make_float2(my, mz);

    float op = opac[g];
    float sv[16];
#pragma unroll
    for (int cc = 0; cc < NC; cc++) sv[cc] = op * semantics[g * NC + cc];
#pragma unroll
    for (int cc = NC; cc < 16; cc++) sv[cc] = 0.0f;
    unsigned w[8];
#pragma unroll
    for (int i = 0; i < 8; i++) {
        __half2 p = __floats2half2_rn(sv[2 * i], sv[2 * i + 1]);
        unsigned u; memcpy(&u, &p, 4);
        w[i] = u;
    }
    g_semh[g][0] = make_uint4(w[0], w[1], w[2], w[3]);
    g_semh[g][1] = make_uint4(w[4], w[5], w[6], w[7]);
}

__device__ __forceinline__ void ldsm_x4_trans(unsigned addr, unsigned &r0, unsigned &r1,
                                              unsigned &r2, unsigned &r3) {
    asm volatile("ldmatrix.sync.aligned.m8n8.x4.trans.shared.b16 {%0,%1,%2,%3}, [%4];"
                 : "=r"(r0), "=r"(r1), "=r"(r2), "=r"(r3) : "r"(addr));
}
__device__ __forceinline__ void mma16816(float* c, unsigned a0, unsigned a1, unsigned a2,
                                         unsigned a3, unsigned b0, unsigned b1) {
    asm volatile("mma.sync.aligned.m16n8k16.row.col.f32.f16.f16.f32 "
                 "{%0,%1,%2,%3}, {%4,%5,%6,%7}, {%8,%9}, {%0,%1,%2,%3};"
                 : "+f"(c[0]), "+f"(c[1]), "+f"(c[2]), "+f"(c[3])
                 : "r"(a0), "r"(a1), "r"(a2), "r"(a3), "r"(b0), "r"(b1));
}

__global__ __launch_bounds__(TPB)
void aggregate_kernel(const float* __restrict__ pts,
                      const float* __restrict__ origin,
                      float* __restrict__ out)
{
    __shared__ int    s_cnt;
    __shared__ short  s_list[NP];
    __shared__ int4   s_box[KB];
    __shared__ float4 s_q0[KB];
    __shared__ float4 s_q1[KB];
    __shared__ float2 s_q2[KB];
    __shared__ uint4  s_semT[KB][2];               // [k][16 ch] fp16, 32B rows
    __shared__ __half s_W[KB * WPAD];              // k-major W tile

    const int t    = threadIdx.x;
    const int wid  = t >> 5;
    const int lane = t & 31;

    if (t == 0) s_cnt = 0;
    __syncthreads();

    const int tlo_x = blockIdx.x * TXC;
    const int tlo_y = blockIdx.y * TYC;
    const int tlo_z = blockIdx.z * TZC;
    const int thi_x = tlo_x + TXC - 1;
    const int thi_y = min(tlo_y + TYC - 1, WW - 1);
    const int thi_z = min(tlo_z + TZC - 1, DDZ - 1);

    // Cooperative coarse cull, warp-aggregated compaction
    for (int g = t; g < NP; g += TPB) {
        int4 bxv = g_box[g];
        bool hit = (bxv.x - bxv.w <= thi_x) && (bxv.x + bxv.w >= tlo_x)
                && (bxv.y - bxv.w <= thi_y) && (bxv.y + bxv.w >= tlo_y)
                && (bxv.z - bxv.w <= thi_z) && (bxv.z + bxv.w >= tlo_z);
        unsigned mask = __ballot_sync(0xffffffffu, hit);
        if (mask) {
            int base;
            if (lane == 0) base = atomicAdd(&s_cnt, __popc(mask));
            base = __shfl_sync(0xffffffffu, base, 0);
            if (hit) s_list[base + __popc(mask & ((1u << lane) - 1u))] = (short)g;
        }
    }
    __syncthreads();
    const int nlist = s_cnt;

    // Thread t owns W rows t (x_loc = t>>6) and t+128 (x_loc+2). row: x=r>>6, y=(r>>3)&7, z=r&7
    const int xl = t >> 6;
    const int yl = (t >> 3) & 7;
    const int zl = t & 7;
    const int yg = tlo_y + yl;
    const int zg = tlo_z + zl;
    const bool valid = (yg < WW) && (zg < DDZ);

    const int xg0 = tlo_x + xl;
    const int pidx0 = (xg0 * WW + yg) * DDZ + zg;
    const int pidx1 = pidx0 + 2 * WW * DDZ;

    const float ox = origin[0], oy = origin[1], oz = origin[2];
    float px0 = 0.f, px1 = 0.f, py = 0.f, pz = 0.f;
    int pix0 = -100000, pix1 = -100000, piy = -100000, piz = -100000;
    if (valid) {
        px0 = pts[pidx0 * 3 + 0];
        py  = pts[pidx0 * 3 + 1];
        pz  = pts[pidx0 * 3 + 2];
        px1 = pts[pidx1 * 3 + 0];
        pix0 = (int)((px0 - ox) / GRID_SZ);
        pix1 = (int)((px1 - ox) / GRID_SZ);
        piy  = (int)((py - oy) / GRID_SZ);
        piz  = (int)((pz - oz) / GRID_SZ);
    }

    // fp32 accumulators: 4 m-tiles x 2 n-tiles x 4 regs
    float acc[4][2][4];
#pragma unroll
    for (int mt = 0; mt < 4; mt++)
#pragma unroll
        for (int nt = 0; nt < 2; nt++)
#pragma unroll
            for (int i = 0; i < 4; i++) acc[mt][nt][i] = 0.0f;

    // smem byte addresses for ldmatrix
    const unsigned sW_base   = (unsigned)__cvta_generic_to_shared(s_W);
    const unsigned semT_base = (unsigned)__cvta_generic_to_shared(&s_semT[0][0]);

    for (int base = 0; base < nlist; base += KB) {
        // Stage this K-batch (dummy entries have r=-1 -> w=0; sem row zeroed)
        if (t < KB) {
            int idx = base + t;
            if (idx < nlist) {
                int g = s_list[idx];
                s_box[t] = g_box[g];
                s_q0[t]  = g_q0[g];
                s_q1[t]  = g_q1[g];
                s_q2[t]  = g_q2[g];
                s_semT[t][0] = g_semh[g][0];
                s_semT[t][1] = g_semh[g][1];
            } else {
                s_box[t] = make_int4(0, 0, 0, -1);
                s_semT[t][0] = make_uint4(0, 0, 0, 0);
                s_semT[t][1] = make_uint4(0, 0, 0, 0);
            }
        }
        __syncthreads();

        // Eval phase: w for rows t and t+128, all KB survivors
#pragma unroll 4
        for (int k = 0; k < KB; k++) {
            const int4 bxv = s_box[k];
            bool iyzok = (abs(piy - bxv.y) <= bxv.w) & (abs(piz - bxv.z) <= bxv.w);
            bool ib0 = iyzok & (abs(pix0 - bxv.x) <= bxv.w);
            bool ib1 = iyzok & (abs(pix1 - bxv.x) <= bxv.w);
            float w0 = 0.0f, w1 = 0.0f;
            if (__any_sync(0xffffffffu, ib0 | ib1)) {
                const float4 q0 = s_q0[k];
                const float4 q1 = s_q1[k];
                const float2 q2 = s_q2[k];
                float dy = py - q2.x;
                float dz = pz - q2.y;
                float syz = fmaf(q0.y * dy, dy, fmaf(q0.z * dz, dz, q1.y * dy * dz));
                float hx  = fmaf(q1.x, dy, q1.z * dz);
                float dx0 = px0 - q1.w;
                float dx1 = px1 - q1.w;
                float e0 = fmaf(fmaf(q0.x, dx0, hx), dx0, syz);
                float e1 = fmaf(fmaf(q0.x, dx1, hx), dx1, syz);
                w0 = ib0 ? __expf(e0) : 0.0f;
                w1 = ib1 ? __expf(e1) : 0.0f;
            }
            s_W[k * WPAD + t]       = __float2half_rn(w0);
            s_W[k * WPAD + t + 128] = __float2half_rn(w1);
        }
        __syncthreads();

        // MMA phase: each warp handles rows 64*wid .. 64*wid+63 (4 m16 tiles)
        {
            unsigned b0, b1, b2, b3;
            unsigned baddr = semT_base + (unsigned)((lane & 15) * 32 + (lane >> 4) * 16);
            ldsm_x4_trans(baddr, b0, b1, b2, b3);

            const int krow = (lane & 7) + ((lane >> 4) << 3);
            const int mcol = ((lane >> 3) & 1) * 8;
#pragma unroll
            for (int mt = 0; mt < 4; mt++) {
                const int mbase = wid * 64 + mt * 16;
                unsigned a0, a1, a2, a3;
                unsigned aaddr = sW_base + (unsigned)(krow * (WPAD * 2) + (mbase + mcol) * 2);
                ldsm_x4_trans(aaddr, a0, a1, a2, a3);
                mma16816(acc[mt][0], a0, a1, a2, a3, b0, b1);
                mma16816(acc[mt][1], a0, a1, a2, a3, b2, b3);
            }
        }
        __syncthreads();   // before next batch overwrites staging/s_W
    }

    // Epilogue: write accumulators
    {
        const int gr  = lane >> 2;
        const int cc2 = (lane & 3) * 2;
#pragma unroll
        for (int mt = 0; mt < 4; mt++) {
#pragma unroll
            for (int h = 0; h < 2; h++) {
                int r = wid * 64 + mt * 16 + gr + h * 8;
                int x = tlo_x + (r >> 6);
                int y = tlo_y + ((r >> 3) & 7);
                int z = tlo_z + (r & 7);
                if (y < WW && z < DDZ) {
                    float* o = out + ((x * WW + y) * DDZ + z) * NC;
                    o[cc2]     = acc[mt][0][2 * h + 0];
                    o[cc2 + 1] = acc[mt][0][2 * h + 1];
                    int cB = 8 + cc2;
                    if (cB < NC)     o[cB]     = acc[mt][1][2 * h + 0];
                    if (cB + 1 < NC) o[cB + 1] = acc[mt][1][2 * h + 1];
                }
            }
        }
    }
}

extern "C" void kernel_launch(void* const* d_in, const int* in_sizes, int n_in,
                              void* d_out, int out_size)
{
    const float* pts      = (const float*)d_in[0];   // [1,129600,3]
    const float* means3D  = (const float*)d_in[1];   // [1,2048,3]
    const float* opac     = (const float*)d_in[2];   // [1,2048]
    const float* sem      = (const float*)d_in[3];   // [1,2048,13]
    const float* scales   = (const float*)d_in[4];   // [1,2048,3]
    const float* cov3D    = (const float*)d_in[5];   // [1,2048,3,3]
    const float* origin   = (const float*)d_in[6];   // [3]
    float* out = (float*)d_out;                      // [129600,13] f32

    precompute_kernel<<<(NP + 255) / 256, 256>>>(means3D, opac, sem, scales, cov3D, origin);

    dim3 grid(HH / TXC, (WW + TYC - 1) / TYC, (DDZ + TZC - 1) / TZC);  // 15, 8, 5
    aggregate_kernel<<<grid, TPB>>>(pts, origin, out);
}

// round 9
// speedup vs baseline: 1.0469x; 1.0469x over previous
#include <cuda_runtime.h>
#include <cuda_fp16.h>

#define HH 60
#define WW 60
#define DDZ 36
#define NP 2048
#define NC 13
#define GRID_SZ 0.08f

#define TXC 4
#define TYC 8
#define TZC 8
#define ROWS 256          // voxels per tile, 1 per thread
#define TPB 256
#define KB 32             // survivors per MMA batch (2 k16 chunks)
#define WPAD 264          // s_W row length in halves -> 528B stride (16B aligned)

// Per-Gaussian precomputed scratch (device globals: no allocation allowed)
__device__ int4   g_box[NP];        // bx, by, bz, r
__device__ float4 g_q0[NP];         // -0.5*ixx, -0.5*iyy, -0.5*izz, pad
__device__ float4 g_q1[NP];         // -ixy, -iyz, -ixz, mx
__device__ float2 g_q2[NP];         // my, mz
__device__ uint4  g_semh[NP][2];    // opacity*semantics as 16 fp16 (13 used, 3 zero)

__global__ void precompute_kernel(const float* __restrict__ means3D,
                                  const float* __restrict__ opac,
                                  const float* __restrict__ semantics,
                                  const float* __restrict__ scales,
                                  const float* __restrict__ cov3D,
                                  const float* __restrict__ origin)
{
    int g = blockIdx.x * blockDim.x + threadIdx.x;
    if (g >= NP) return;

    const float* cv = cov3D + g * 9;
    float a = cv[0], b = cv[4], c = cv[8];
    float d = cv[1], e = cv[5], f = cv[2];
    float det = a * (b * c - e * e) - d * (d * c - e * f) + f * (d * e - b * f);
    float ixx = (b * c - e * e) / det;
    float iyy = (a * c - f * f) / det;
    float izz = (a * b - d * d) / det;
    float ixy = (e * f - d * c) / det;
    float iyz = (d * f - a * e) / det;
    float ixz = (d * e - b * f) / det;

    float ox = origin[0], oy = origin[1], oz = origin[2];
    float mx = means3D[g * 3 + 0];
    float my = means3D[g * 3 + 1];
    float mz = means3D[g * 3 + 2];

    float s = fmaxf(scales[g * 3 + 0], fmaxf(scales[g * 3 + 1], scales[g * 3 + 2]));
    int r = (int)ceilf(s * 3.0f / GRID_SZ);

    g_box[g] = make_int4((int)((mx - ox) / GRID_SZ),
                         (int)((my - oy) / GRID_SZ),
                         (int)((mz - oz) / GRID_SZ), r);
    g_q0[g] = make_float4(-0.5f * ixx, -0.5f * iyy, -0.5f * izz, 0.0f);
    g_q1[g] = make_float4(-ixy, -iyz, -ixz, mx);
    g_q2[g] = make_float2(my, mz);

    float op = opac[g];
    float sv[16];
#pragma unroll
    for (int cc = 0; cc < NC; cc++) sv[cc] = op * semantics[g * NC + cc];
#pragma unroll
    for (int cc = NC; cc < 16; cc++) sv[cc] = 0.0f;
    unsigned w[8];
#pragma unroll
    for (int i = 0; i < 8; i++) {
        __half2 p = __floats2half2_rn(sv[2 * i], sv[2 * i + 1]);
        unsigned u; memcpy(&u, &p, 4);
        w[i] = u;
    }
    g_semh[g][0] = make_uint4(w[0], w[1], w[2], w[3]);
    g_semh[g][1] = make_uint4(w[4], w[5], w[6], w[7]);
}

__device__ __forceinline__ void ldsm_x4_trans(unsigned addr, unsigned &r0, unsigned &r1,
                                              unsigned &r2, unsigned &r3) {
    asm volatile("ldmatrix.sync.aligned.m8n8.x4.trans.shared.b16 {%0,%1,%2,%3}, [%4];"
                 : "=r"(r0), "=r"(r1), "=r"(r2), "=r"(r3) : "r"(addr));
}
__device__ __forceinline__ void mma16816(float* c, unsigned a0, unsigned a1, unsigned a2,
                                         unsigned a3, unsigned b0, unsigned b1) {
    asm volatile("mma.sync.aligned.m16n8k16.row.col.f32.f16.f16.f32 "
                 "{%0,%1,%2,%3}, {%4,%5,%6,%7}, {%8,%9}, {%0,%1,%2,%3};"
                 : "+f"(c[0]), "+f"(c[1]), "+f"(c[2]), "+f"(c[3])
                 : "r"(a0), "r"(a1), "r"(a2), "r"(a3), "r"(b0), "r"(b1));
}

__global__ __launch_bounds__(TPB)
void aggregate_kernel(const float* __restrict__ pts,
                      const float* __restrict__ origin,
                      float* __restrict__ out)
{
    __shared__ int    s_cnt;
    __shared__ short  s_list[NP];
    __shared__ int4   s_box[KB];
    __shared__ float4 s_q0[KB];
    __shared__ float4 s_q1[KB];
    __shared__ float2 s_q2[KB];
    __shared__ uint4  s_semT[KB][2];               // [k][16 ch] fp16, 32B rows
    __shared__ __half s_W[KB * WPAD];              // k-major W tile

    const int t    = threadIdx.x;
    const int wid  = t >> 5;
    const int lane = t & 31;

    if (t == 0) s_cnt = 0;
    __syncthreads();

    const int tlo_x = blockIdx.x * TXC;
    const int tlo_y = blockIdx.y * TYC;
    const int tlo_z = blockIdx.z * TZC;
    const int thi_x = tlo_x + TXC - 1;
    const int thi_y = min(tlo_y + TYC - 1, WW - 1);
    const int thi_z = min(tlo_z + TZC - 1, DDZ - 1);

    // Cooperative coarse cull, warp-aggregated compaction
    for (int g = t; g < NP; g += TPB) {
        int4 bxv = g_box[g];
        bool hit = (bxv.x - bxv.w <= thi_x) && (bxv.x + bxv.w >= tlo_x)
                && (bxv.y - bxv.w <= thi_y) && (bxv.y + bxv.w >= tlo_y)
                && (bxv.z - bxv.w <= thi_z) && (bxv.z + bxv.w >= tlo_z);
        unsigned mask = __ballot_sync(0xffffffffu, hit);
        if (mask) {
            int base;
            if (lane == 0) base = atomicAdd(&s_cnt, __popc(mask));
            base = __shfl_sync(0xffffffffu, base, 0);
            if (hit) s_list[base + __popc(mask & ((1u << lane) - 1u))] = (short)g;
        }
    }
    __syncthreads();
    const int nlist = s_cnt;

    // Thread t owns W row t. row r: x=r>>6, y=(r>>3)&7, z=r&7
    const int yg = tlo_y + ((t >> 3) & 7);
    const int zg = tlo_z + (t & 7);
    const int xg = tlo_x + (t >> 6);
    const bool valid = (yg < WW) && (zg < DDZ);

    const int pidx = (xg * WW + yg) * DDZ + zg;

    const float ox = origin[0], oy = origin[1], oz = origin[2];
    float px = 0.f, py = 0.f, pz = 0.f;
    int pix = -100000, piy = -100000, piz = -100000;
    if (valid) {
        px = pts[pidx * 3 + 0];
        py = pts[pidx * 3 + 1];
        pz = pts[pidx * 3 + 2];
        pix = (int)((px - ox) / GRID_SZ);
        piy = (int)((py - oy) / GRID_SZ);
        piz = (int)((pz - oz) / GRID_SZ);
    }

    // fp32 accumulators: 2 m-tiles x 2 n-tiles x 4 regs (warp owns rows 32*wid..32*wid+31)
    float acc[2][2][4];
#pragma unroll
    for (int mt = 0; mt < 2; mt++)
#pragma unroll
        for (int nt = 0; nt < 2; nt++)
#pragma unroll
            for (int i = 0; i < 4; i++) acc[mt][nt][i] = 0.0f;

    const unsigned sW_base   = (unsigned)__cvta_generic_to_shared(s_W);
    const unsigned semT_base = (unsigned)__cvta_generic_to_shared(&s_semT[0][0]);

    for (int base = 0; base < nlist; base += KB) {
        // Stage this K-batch (dummy entries: r=-1 -> w=0, sem rows zero)
        if (t < KB) {
            int idx = base + t;
            if (idx < nlist) {
                int g = s_list[idx];
                s_box[t] = g_box[g];
                s_q0[t]  = g_q0[g];
                s_q1[t]  = g_q1[g];
                s_q2[t]  = g_q2[g];
                s_semT[t][0] = g_semh[g][0];
                s_semT[t][1] = g_semh[g][1];
            } else {
                s_box[t] = make_int4(0, 0, 0, -1);
                s_semT[t][0] = make_uint4(0, 0, 0, 0);
                s_semT[t][1] = make_uint4(0, 0, 0, 0);
            }
        }
        __syncthreads();

        // Eval phase: w for row t, all KB survivors
#pragma unroll 4
        for (int k = 0; k < KB; k++) {
            const int4 bxv = s_box[k];
            bool ib = (abs(pix - bxv.x) <= bxv.w)
                    & (abs(piy - bxv.y) <= bxv.w)
                    & (abs(piz - bxv.z) <= bxv.w);
            float w = 0.0f;
            if (__any_sync(0xffffffffu, ib)) {
                const float4 q0 = s_q0[k];
                const float4 q1 = s_q1[k];
                const float2 q2 = s_q2[k];
                float dx = px - q1.w;
                float dy = py - q2.x;
                float dz = pz - q2.y;
                float e = fmaf(q0.x * dx, dx,
                          fmaf(q0.y * dy, dy,
                          fmaf(q0.z * dz, dz,
                          fmaf(q1.x * dx, dy,
                          fmaf(q1.y * dy, dz, q1.z * dx * dz)))));
                w = ib ? __expf(e) : 0.0f;
            }
            s_W[k * WPAD + t] = __float2half_rn(w);
        }
        __syncthreads();

        // MMA phase: warp w handles rows 32*wid..32*wid+31 (2 m16 tiles), 2 k16 chunks
#pragma unroll
        for (int kc = 0; kc < 2; kc++) {
            unsigned b0, b1, b2, b3;
            unsigned baddr = semT_base +
                (unsigned)(((lane & 15) + kc * 16) * 32 + (lane >> 4) * 16);
            ldsm_x4_trans(baddr, b0, b1, b2, b3);

            const int krow = (lane & 7) + ((lane >> 4) << 3) + kc * 16;
            const int mcol = ((lane >> 3) & 1) * 8;
#pragma unroll
            for (int mt = 0; mt < 2; mt++) {
                const int mbase = wid * 32 + mt * 16;
                unsigned a0, a1, a2, a3;
                unsigned aaddr = sW_base + (unsigned)(krow * (WPAD * 2) + (mbase + mcol) * 2);
                ldsm_x4_trans(aaddr, a0, a1, a2, a3);
                mma16816(acc[mt][0], a0, a1, a2, a3, b0, b1);
                mma16816(acc[mt][1], a0, a1, a2, a3, b2, b3);
            }
        }
        __syncthreads();   // before next batch overwrites staging/s_W
    }

    // Epilogue: write accumulators
    {
        const int gr  = lane >> 2;
        const int cc2 = (lane & 3) * 2;
#pragma unroll
        for (int mt = 0; mt < 2; mt++) {
#pragma unroll
            for (int h = 0; h < 2; h++) {
                int r = wid * 32 + mt * 16 + gr + h * 8;
                int x = tlo_x + (r >> 6);
                int y = tlo_y + ((r >> 3) & 7);
                int z = tlo_z + (r & 7);
                if (y < WW && z < DDZ) {
                    float* o = out + ((x * WW + y) * DDZ + z) * NC;
                    o[cc2]     = acc[mt][0][2 * h + 0];
                    o[cc2 + 1] = acc[mt][0][2 * h + 1];
                    int cB = 8 + cc2;
                    if (cB < NC)     o[cB]     = acc[mt][1][2 * h + 0];
                    if (cB + 1 < NC) o[cB + 1] = acc[mt][1][2 * h + 1];
                }
            }
        }
    }
}

extern "C" void kernel_launch(void* const* d_in, const int* in_sizes, int n_in,
                              void* d_out, int out_size)
{
    const float* pts      = (const float*)d_in[0];   // [1,129600,3]
    const float* means3D  = (const float*)d_in[1];   // [1,2048,3]
    const float* opac     = (const float*)d_in[2];   // [1,2048]
    const float* sem      = (const float*)d_in[3];   // [1,2048,13]
    const float* scales   = (const float*)d_in[4];   // [1,2048,3]
    const float* cov3D    = (const float*)d_in[5];   // [1,2048,3,3]
    const float* origin   = (const float*)d_in[6];   // [3]
    float* out = (float*)d_out;                      // [129600,13] f32

    precompute_kernel<<<(NP + 255) / 256, 256>>>(means3D, opac, sem, scales, cov3D, origin);

    dim3 grid(HH / TXC, (WW + TYC - 1) / TYC, (DDZ + TZC - 1) / TZC);  // 15, 8, 5
    aggregate_kernel<<<grid, TPB>>>(pts, origin, out);
}

// round 10
// speedup vs baseline: 1.1087x; 1.0591x over previous
#include <cuda_runtime.h>
#include <cuda_fp16.h>

#define HH 60
#define WW 60
#define DDZ 36
#define NP 2048
#define NC 13
#define GRID_SZ 0.08f
#define LOG2E 1.4426950408889634f

#define TXC 4
#define TYC 8
#define TZC 8
#define TPB 256
#define CH  128            // survivors staged per block-sync
#define WROW 40            // W row stride in halves (80B, ldsm conflict-free)

// Per-Gaussian precomputed scratch (device globals: no allocation allowed)
__device__ int4   g_box[NP];        // bx, by, bz, r  (cull only)
__device__ float4 g_q0[NP];         // a_xx, a_yy, a_zz, lo_packed(u8 x3)
__device__ float4 g_q1[NP];         // a_xy, a_yz, a_xz, hi_packed(u8 x3)
__device__ float4 g_q2[NP];         // mx, my, mz, 0
__device__ uint4  g_semh[NP][2];    // opacity*semantics as 16 fp16 (13 used, 3 zero)

__global__ void precompute_kernel(const float* __restrict__ means3D,
                                  const float* __restrict__ opac,
                                  const float* __restrict__ semantics,
                                  const float* __restrict__ scales,
                                  const float* __restrict__ cov3D,
                                  const float* __restrict__ origin)
{
    int g = blockIdx.x * blockDim.x + threadIdx.x;
    if (g >= NP) return;

    const float* cv = cov3D + g * 9;
    float a = cv[0], b = cv[4], c = cv[8];
    float d = cv[1], e = cv[5], f = cv[2];
    float det = a * (b * c - e * e) - d * (d * c - e * f) + f * (d * e - b * f);
    float ixx = (b * c - e * e) / det;
    float iyy = (a * c - f * f) / det;
    float izz = (a * b - d * d) / det;
    float ixy = (e * f - d * c) / det;
    float iyz = (d * f - a * e) / det;
    float ixz = (d * e - b * f) / det;

    float ox = origin[0], oy = origin[1], oz = origin[2];
    float mx = means3D[g * 3 + 0];
    float my = means3D[g * 3 + 1];
    float mz = means3D[g * 3 + 2];

    float s = fmaxf(scales[g * 3 + 0], fmaxf(scales[g * 3 + 1], scales[g * 3 + 2]));
    int r = (int)ceilf(s * 3.0f / GRID_SZ);

    int bx = (int)((mx - ox) / GRID_SZ);
    int by = (int)((my - oy) / GRID_SZ);
    int bz = (int)((mz - oz) / GRID_SZ);
    g_box[g] = make_int4(bx, by, bz, r);

    // packed u8 bounds (clamped to [0,255]); point coords are in [0,59]
    unsigned lo = (unsigned)max(bx - r, 0) | ((unsigned)max(by - r, 0) << 8)
                | ((unsigned)max(bz - r, 0) << 16);
    unsigned hi = (unsigned)min(bx + r, 255) | ((unsigned)min(by + r, 255) << 8)
                | ((unsigned)min(bz + r, 255) << 16);

    // fold -0.5 and log2e: w = exp2(e)
    g_q0[g] = make_float4(-0.5f * ixx * LOG2E, -0.5f * iyy * LOG2E, -0.5f * izz * LOG2E,
                          __uint_as_float(lo));
    g_q1[g] = make_float4(-ixy * LOG2E, -iyz * LOG2E, -ixz * LOG2E,
                          __uint_as_float(hi));
    g_q2[g] = make_float4(mx, my, mz, 0.0f);

    float op = opac[g];
    float sv[16];
#pragma unroll
    for (int cc = 0; cc < NC; cc++) sv[cc] = op * semantics[g * NC + cc];
#pragma unroll
    for (int cc = NC; cc < 16; cc++) sv[cc] = 0.0f;
    unsigned w[8];
#pragma unroll
    for (int i = 0; i < 8; i++) {
        __half2 p = __floats2half2_rn(sv[2 * i], sv[2 * i + 1]);
        unsigned u; memcpy(&u, &p, 4);
        w[i] = u;
    }
    g_semh[g][0] = make_uint4(w[0], w[1], w[2], w[3]);
    g_semh[g][1] = make_uint4(w[4], w[5], w[6], w[7]);
}

__device__ __forceinline__ void ldsm_x4_trans(unsigned addr, unsigned &r0, unsigned &r1,
                                              unsigned &r2, unsigned &r3) {
    asm volatile("ldmatrix.sync.aligned.m8n8.x4.trans.shared.b16 {%0,%1,%2,%3}, [%4];"
                 : "=r"(r0), "=r"(r1), "=r"(r2), "=r"(r3) : "r"(addr));
}
__device__ __forceinline__ void mma16816(float* c, unsigned a0, unsigned a1, unsigned a2,
                                         unsigned a3, unsigned b0, unsigned b1) {
    asm volatile("mma.sync.aligned.m16n8k16.row.col.f32.f16.f16.f32 "
                 "{%0,%1,%2,%3}, {%4,%5,%6,%7}, {%8,%9}, {%0,%1,%2,%3};"
                 : "+f"(c[0]), "+f"(c[1]), "+f"(c[2]), "+f"(c[3])
                 : "r"(a0), "r"(a1), "r"(a2), "r"(a3), "r"(b0), "r"(b1));
}

__global__ __launch_bounds__(TPB)
void aggregate_kernel(const float* __restrict__ pts,
                      const float* __restrict__ origin,
                      float* __restrict__ out)
{
    __shared__ int    s_cnt;
    __shared__ short  s_list[NP];
    __shared__ float4 s_q0[CH];
    __shared__ float4 s_q1[CH];
    __shared__ float4 s_q2[CH];
    __shared__ uint4  s_semT[CH][2];             // [k][16 ch] fp16, 32B rows
    __shared__ __half s_W[8 * 16 * WROW];        // per-warp 16k x 40m private tiles

    const int t    = threadIdx.x;
    const int wid  = t >> 5;
    const int lane = t & 31;

    if (t == 0) s_cnt = 0;
    __syncthreads();

    const int tlo_x = blockIdx.x * TXC;
    const int tlo_y = blockIdx.y * TYC;
    const int tlo_z = blockIdx.z * TZC;
    const int thi_x = tlo_x + TXC - 1;
    const int thi_y = min(tlo_y + TYC - 1, WW - 1);
    const int thi_z = min(tlo_z + TZC - 1, DDZ - 1);

    // Cooperative coarse cull, warp-aggregated compaction
    for (int g = t; g < NP; g += TPB) {
        int4 bxv = g_box[g];
        bool hit = (bxv.x - bxv.w <= thi_x) && (bxv.x + bxv.w >= tlo_x)
                && (bxv.y - bxv.w <= thi_y) && (bxv.y + bxv.w >= tlo_y)
                && (bxv.z - bxv.w <= thi_z) && (bxv.z + bxv.w >= tlo_z);
        unsigned mask = __ballot_sync(0xffffffffu, hit);
        if (mask) {
            int base;
            if (lane == 0) base = atomicAdd(&s_cnt, __popc(mask));
            base = __shfl_sync(0xffffffffu, base, 0);
            if (hit) s_list[base + __popc(mask & ((1u << lane) - 1u))] = (short)g;
        }
    }
    __syncthreads();
    const int nlist = s_cnt;

    // Thread t owns W row t. row r: x=r>>6, y=(r>>3)&7, z=r&7
    const int yg = tlo_y + ((t >> 3) & 7);
    const int zg = tlo_z + (t & 7);
    const int xg = tlo_x + (t >> 6);
    const bool valid = (yg < WW) && (zg < DDZ);
    const int pidx = (xg * WW + yg) * DDZ + zg;

    const float ox = origin[0], oy = origin[1], oz = origin[2];
    float px = 0.f, py = 0.f, pz = 0.f;
    unsigned ppack = 0x00FFFFFFu;                 // never inbox for invalid lanes
    if (valid) {
        px = pts[pidx * 3 + 0];
        py = pts[pidx * 3 + 1];
        pz = pts[pidx * 3 + 2];
        int pix = (int)((px - ox) / GRID_SZ);
        int piy = (int)((py - oy) / GRID_SZ);
        int piz = (int)((pz - oz) / GRID_SZ);
        ppack = (unsigned)pix | ((unsigned)piy << 8) | ((unsigned)piz << 16);
    }

    // fp32 accumulators: 2 m-tiles x 2 n-tiles x 4 regs (warp owns rows 32*wid..+31)
    float acc[2][2][4];
#pragma unroll
    for (int mt = 0; mt < 2; mt++)
#pragma unroll
        for (int nt = 0; nt < 2; nt++)
#pragma unroll
            for (int i = 0; i < 4; i++) acc[mt][nt][i] = 0.0f;

    const unsigned semT_base = (unsigned)__cvta_generic_to_shared(&s_semT[0][0]);
    const unsigned wbase = (unsigned)__cvta_generic_to_shared(s_W) + wid * (16 * WROW * 2);
    __half* wbuf = s_W + wid * (16 * WROW);

    for (int cbase = 0; cbase < nlist; cbase += CH) {
        const int cnt  = min(CH, nlist - cbase);
        const int nk16 = (cnt + 15) >> 4;
        const int staged = nk16 << 4;

        // Stage chunk (dummies: lo=0x00FFFFFF never matches, sem zero)
        if (t < staged) {
            if (t < cnt) {
                int g = s_list[cbase + t];
                s_q0[t] = g_q0[g];
                s_q1[t] = g_q1[g];
                s_q2[t] = g_q2[g];
                s_semT[t][0] = g_semh[g][0];
                s_semT[t][1] = g_semh[g][1];
            } else {
                s_q0[t] = make_float4(0.f, 0.f, 0.f, __uint_as_float(0x00FFFFFFu));
                s_q1[t] = make_float4(0.f, 0.f, 0.f, 0.f);
                s_q2[t] = make_float4(0.f, 0.f, 0.f, 0.f);
                s_semT[t][0] = make_uint4(0, 0, 0, 0);
                s_semT[t][1] = make_uint4(0, 0, 0, 0);
            }
        }
        __syncthreads();

        // Warp-private pipeline over k16 chunks: eval -> ldsm -> mma (no block syncs)
        for (int c = 0; c < nk16; c++) {
            const int kb = c << 4;
#pragma unroll 4
            for (int k = 0; k < 16; k++) {
                const int kk = kb + k;
                float4 q0 = s_q0[kk];
                float4 q1 = s_q1[kk];
                unsigned lo = __float_as_uint(q0.w);
                unsigned hi = __float_as_uint(q1.w);
                bool ib = ((__vcmpgeu4(ppack, lo) & __vcmpleu4(ppack, hi)) == 0xFFFFFFFFu);
                float w = 0.0f;
                if (__any_sync(0xffffffffu, ib)) {
                    float4 q2 = s_q2[kk];
                    float dx = px - q2.x;
                    float dy = py - q2.y;
                    float dz = pz - q2.z;
                    float i1 = fmaf(q0.x, dx, fmaf(q1.x, dy, q1.z * dz));
                    float i2 = fmaf(q0.y, dy, q1.y * dz);
                    float e  = fmaf(dx, i1, fmaf(dy, i2, (q0.z * dz) * dz));
                    float ww;
                    asm("ex2.approx.ftz.f32 %0, %1;" : "=f"(ww) : "f"(e));
                    w = ib ? ww : 0.0f;
                }
                wbuf[k * WROW + lane] = __float2half_rn(w);
            }
            __syncwarp();

            // B fragments (sem cols 0-7, 8-15) for this k16
            unsigned b0, b1, b2, b3;
            unsigned baddr = semT_base + (unsigned)((kb + (lane & 15)) * 32 + ((lane >> 4) << 4));
            ldsm_x4_trans(baddr, b0, b1, b2, b3);

            // A fragments from private W (k-major, 80B rows), 2 m16 tiles
            const int krow = (lane & 7) + ((lane >> 4) << 3);
            const int mcol = ((lane >> 3) & 1) * 8;
#pragma unroll
            for (int mt = 0; mt < 2; mt++) {
                unsigned a0, a1, a2, a3;
                unsigned aaddr = wbase + (unsigned)(krow * (WROW * 2) + (mt * 16 + mcol) * 2);
                ldsm_x4_trans(aaddr, a0, a1, a2, a3);
                mma16816(acc[mt][0], a0, a1, a2, a3, b0, b1);
                mma16816(acc[mt][1], a0, a1, a2, a3, b2, b3);
            }
            __syncwarp();   // before next c overwrites wbuf
        }
        __syncthreads();    // before restaging s_q*/s_semT
    }

    // Epilogue: write accumulators (warp rows 32*wid..+31)
    {
        const int gr  = lane >> 2;
        const int cc2 = (lane & 3) * 2;
#pragma unroll
        for (int mt = 0; mt < 2; mt++) {
#pragma unroll
            for (int h = 0; h < 2; h++) {
                int r = wid * 32 + mt * 16 + gr + h * 8;
                int x = tlo_x + (r >> 6);
                int y = tlo_y + ((r >> 3) & 7);
                int z = tlo_z + (r & 7);
                if (y < WW && z < DDZ) {
                    float* o = out + ((x * WW + y) * DDZ + z) * NC;
                    o[cc2]     = acc[mt][0][2 * h + 0];
                    o[cc2 + 1] = acc[mt][0][2 * h + 1];
                    int cB = 8 + cc2;
                    if (cB < NC)     o[cB]     = acc[mt][1][2 * h + 0];
                    if (cB + 1 < NC) o[cB + 1] = acc[mt][1][2 * h + 1];
                }
            }
        }
    }
}

extern "C" void kernel_launch(void* const* d_in, const int* in_sizes, int n_in,
                              void* d_out, int out_size)
{
    const float* pts      = (const float*)d_in[0];   // [1,129600,3]
    const float* means3D  = (const float*)d_in[1];   // [1,2048,3]
    const float* opac     = (const float*)d_in[2];   // [1,2048]
    const float* sem      = (const float*)d_in[3];   // [1,2048,13]
    const float* scales   = (const float*)d_in[4];   // [1,2048,3]
    const float* cov3D    = (const float*)d_in[5];   // [1,2048,3,3]
    const float* origin   = (const float*)d_in[6];   // [3]
    float* out = (float*)d_out;                      // [129600,13] f32

    precompute_kernel<<<(NP + 255) / 256, 256>>>(means3D, opac, sem, scales, cov3D, origin);

    dim3 grid(HH / TXC, (WW + TYC - 1) / TYC, (DDZ + TZC - 1) / TZC);  // 15, 8, 5
    aggregate_kernel<<<grid, TPB>>>(pts, origin, out);
}

// round 12
// speedup vs baseline: 1.1097x; 1.0009x over previous
#include <cuda_runtime.h>
#include <cuda_fp16.h>

#define HH 60
#define WW 60
#define DDZ 36
#define NVOX (HH*WW*DDZ)
#define NP 2048
#define NC 13
#define GRID_SZ 0.08f
#define LOG2E 1.4426950408889634f

#define TXC 4
#define TYC 8
#define TZC 8
#define TPB 128
#define CH  64             // survivors staged per block-sync
#define WROW 72            // W row stride in halves (144B, ldsm conflict-free)

// Per-Gaussian precomputed scratch (device globals: no allocation allowed)
__device__ int4   g_box[NP];        // bx, by, bz, r  (cull only)
__device__ uint2  g_bnd[NP];        // packed u8 lo / hi bounds
__device__ float4 g_q0[NP];         // a_xx, a_yy, a_zz, -
__device__ float4 g_q1[NP];         // a_xy, a_yz, a_xz, -
__device__ float4 g_q2[NP];         // mx, my, mz, -
__device__ uint4  g_semh[NP][2];    // opacity*semantics as 16 fp16 (13 used, 3 zero)
__device__ float4 g_part4[2][NVOX * NC / 4];   // k-split partial sums

__global__ void precompute_kernel(const float* __restrict__ means3D,
                                  const float* __restrict__ opac,
                                  const float* __restrict__ semantics,
                                  const float* __restrict__ scales,
                                  const float* __restrict__ cov3D,
                                  const float* __restrict__ origin)
{
    int g = blockIdx.x * blockDim.x + threadIdx.x;
    if (g >= NP) return;

    const float* cv = cov3D + g * 9;
    float a = cv[0], b = cv[4], c = cv[8];
    float d = cv[1], e = cv[5], f = cv[2];
    float det = a * (b * c - e * e) - d * (d * c - e * f) + f * (d * e - b * f);
    float ixx = (b * c - e * e) / det;
    float iyy = (a * c - f * f) / det;
    float izz = (a * b - d * d) / det;
    float ixy = (e * f - d * c) / det;
    float iyz = (d * f - a * e) / det;
    float ixz = (d * e - b * f) / det;

    float ox = origin[0], oy = origin[1], oz = origin[2];
    float mx = means3D[g * 3 + 0];
    float my = means3D[g * 3 + 1];
    float mz = means3D[g * 3 + 2];

    float s = fmaxf(scales[g * 3 + 0], fmaxf(scales[g * 3 + 1], scales[g * 3 + 2]));
    int r = (int)ceilf(s * 3.0f / GRID_SZ);

    int bx = (int)((mx - ox) / GRID_SZ);
    int by = (int)((my - oy) / GRID_SZ);
    int bz = (int)((mz - oz) / GRID_SZ);
    g_box[g] = make_int4(bx, by, bz, r);

    unsigned lo = (unsigned)max(bx - r, 0) | ((unsigned)max(by - r, 0) << 8)
                | ((unsigned)max(bz - r, 0) << 16);
    unsigned hi = (unsigned)min(bx + r, 255) | ((unsigned)min(by + r, 255) << 8)
                | ((unsigned)min(bz + r, 255) << 16);
    g_bnd[g] = make_uint2(lo, hi);

    // fold -0.5 and log2e: w = exp2(e)
    g_q0[g] = make_float4(-0.5f * ixx * LOG2E, -0.5f * iyy * LOG2E, -0.5f * izz * LOG2E, 0.f);
    g_q1[g] = make_float4(-ixy * LOG2E, -iyz * LOG2E, -ixz * LOG2E, 0.f);
    g_q2[g] = make_float4(mx, my, mz, 0.0f);

    float op = opac[g];
    float sv[16];
#pragma unroll
    for (int cc = 0; cc < NC; cc++) sv[cc] = op * semantics[g * NC + cc];
#pragma unroll
    for (int cc = NC; cc < 16; cc++) sv[cc] = 0.0f;
    unsigned w[8];
#pragma unroll
    for (int i = 0; i < 8; i++) {
        __half2 p = __floats2half2_rn(sv[2 * i], sv[2 * i + 1]);
        unsigned u; memcpy(&u, &p, 4);
        w[i] = u;
    }
    g_semh[g][0] = make_uint4(w[0], w[1], w[2], w[3]);
    g_semh[g][1] = make_uint4(w[4], w[5], w[6], w[7]);
}

__device__ __forceinline__ void ldsm_x4_trans(unsigned addr, unsigned &r0, unsigned &r1,
                                              unsigned &r2, unsigned &r3) {
    asm volatile("ldmatrix.sync.aligned.m8n8.x4.trans.shared.b16 {%0,%1,%2,%3}, [%4];"
                 : "=r"(r0), "=r"(r1), "=r"(r2), "=r"(r3) : "r"(addr));
}
__device__ __forceinline__ void mma16816(float* c, unsigned a0, unsigned a1, unsigned a2,
                                         unsigned a3, unsigned b0, unsigned b1) {
    asm volatile("mma.sync.aligned.m16n8k16.row.col.f32.f16.f16.f32 "
                 "{%0,%1,%2,%3}, {%4,%5,%6,%7}, {%8,%9}, {%0,%1,%2,%3};"
                 : "+f"(c[0]), "+f"(c[1]), "+f"(c[2]), "+f"(c[3])
                 : "r"(a0), "r"(a1), "r"(a2), "r"(a3), "r"(b0), "r"(b1));
}

__global__ __launch_bounds__(TPB)
void aggregate_kernel(const float* __restrict__ pts,
                      const float* __restrict__ origin)
{
    __shared__ int    s_cnt;
    __shared__ short  s_list[NP / 2 + 64];
    __shared__ uint2  s_bnd[CH];
    __shared__ float4 s_q0[CH];
    __shared__ float4 s_q1[CH];
    __shared__ float4 s_q2[CH];
    __shared__ uint4  s_semT[CH][2];              // [k][16 ch] fp16, 32B rows
    __shared__ __half s_W[4 * 16 * WROW];         // per-warp 16k x 72m private tiles

    const int t    = threadIdx.x;
    const int wid  = t >> 5;
    const int lane = t & 31;

    if (t == 0) s_cnt = 0;
    __syncthreads();

    const int tile_z = blockIdx.z >> 1;
    const int ks     = blockIdx.z & 1;            // k-split: this block owns g with (g&1)==ks

    const int tlo_x = blockIdx.x * TXC;
    const int tlo_y = blockIdx.y * TYC;
    const int tlo_z = tile_z * TZC;
    const int thi_x = tlo_x + TXC - 1;
    const int thi_y = min(tlo_y + TYC - 1, WW - 1);
    const int thi_z = min(tlo_z + TZC - 1, DDZ - 1);

    // Cooperative coarse cull over this block's parity class (deterministic split:
    // membership depends only on g, never on list order)
    for (int g = 2 * t + ks; g < NP; g += 2 * TPB) {
        int4 bxv = g_box[g];
        bool hit = (bxv.x - bxv.w <= thi_x) && (bxv.x + bxv.w >= tlo_x)
                && (bxv.y - bxv.w <= thi_y) && (bxv.y + bxv.w >= tlo_y)
                && (bxv.z - bxv.w <= thi_z) && (bxv.z + bxv.w >= tlo_z);
        unsigned mask = __ballot_sync(0xffffffffu, hit);
        if (mask) {
            int base;
            if (lane == 0) base = atomicAdd(&s_cnt, __popc(mask));
            base = __shfl_sync(0xffffffffu, base, 0);
            if (hit) s_list[base + __popc(mask & ((1u << lane) - 1u))] = (short)g;
        }
    }
    __syncthreads();
    const int nlist = s_cnt;

    // Lane l of warp w evals W rows r0 = 64w + l and r1 = r0 + 32 (same x,z; y1 = y0+4)
    const int xg = tlo_x + wid;
    const int zg = tlo_z + (lane & 7);
    const int yg0 = tlo_y + (lane >> 3);
    const int yg1 = yg0 + 4;
    const bool valid0 = (yg0 < WW) && (zg < DDZ);
    const bool valid1 = (yg1 < WW) && (zg < DDZ);
    const int pidx0 = (xg * WW + yg0) * DDZ + zg;
    const int pidx1 = (xg * WW + yg1) * DDZ + zg;

    const float ox = origin[0], oy = origin[1], oz = origin[2];
    float px = 0.f, py0 = 0.f, py1 = 0.f, pz = 0.f;
    unsigned pp0 = 0x00FFFFFFu, pp1 = 0x00FFFFFFu;   // never inbox when invalid
    if (valid0) {
        px  = pts[pidx0 * 3 + 0];
        py0 = pts[pidx0 * 3 + 1];
        pz  = pts[pidx0 * 3 + 2];
        int pix = (int)((px - ox) / GRID_SZ);
        int piy = (int)((py0 - oy) / GRID_SZ);
        int piz = (int)((pz - oz) / GRID_SZ);
        pp0 = (unsigned)pix | ((unsigned)piy << 8) | ((unsigned)piz << 16);
        if (valid1) {
            py1 = pts[pidx1 * 3 + 1];
            int piy1 = (int)((py1 - oy) / GRID_SZ);
            pp1 = (unsigned)pix | ((unsigned)piy1 << 8) | ((unsigned)piz << 16);
        }
    }

    // fp32 accumulators: 4 m-tiles x 2 n-tiles x 4 regs (warp owns rows 64*wid..+63)
    float acc[4][2][4];
#pragma unroll
    for (int mt = 0; mt < 4; mt++)
#pragma unroll
        for (int nt = 0; nt < 2; nt++)
#pragma unroll
            for (int i = 0; i < 4; i++) acc[mt][nt][i] = 0.0f;

    const unsigned semT_base = (unsigned)__cvta_generic_to_shared(&s_semT[0][0]);
    const unsigned wbase = (unsigned)__cvta_generic_to_shared(s_W) + wid * (16 * WROW * 2);
    __half* wbuf = s_W + wid * (16 * WROW);

    for (int cbase = 0; cbase < nlist; cbase += CH) {
        const int cnt  = min(CH, nlist - cbase);
        const int nk16 = (cnt + 15) >> 4;
        const int staged = nk16 << 4;

        // Stage this chunk (dummies: bounds that never match, sem zero)
        if (t < staged) {
            int j = cbase + t;
            if (j < nlist) {
                int g = s_list[j];
                s_bnd[t] = g_bnd[g];
                s_q0[t]  = g_q0[g];
                s_q1[t]  = g_q1[g];
                s_q2[t]  = g_q2[g];
                s_semT[t][0] = g_semh[g][0];
                s_semT[t][1] = g_semh[g][1];
            } else {
                s_bnd[t] = make_uint2(0x00FFFFFFu, 0u);   // lo > hi: never matches
                s_semT[t][0] = make_uint4(0, 0, 0, 0);
                s_semT[t][1] = make_uint4(0, 0, 0, 0);
            }
        }
        __syncthreads();

        // Warp-private pipeline over k16 chunks: eval -> ldsm -> mma (no block syncs)
        for (int c = 0; c < nk16; c++) {
            const int kb = c << 4;
#pragma unroll 4
            for (int k = 0; k < 16; k++) {
                const int kk = kb + k;
                uint2 bnd = s_bnd[kk];
                bool ib0 = ((__vcmpgeu4(pp0, bnd.x) & __vcmpleu4(pp0, bnd.y)) == 0xFFFFFFFFu);
                bool ib1 = ((__vcmpgeu4(pp1, bnd.x) & __vcmpleu4(pp1, bnd.y)) == 0xFFFFFFFFu);
                float w0 = 0.0f, w1 = 0.0f;
                if (__any_sync(0xffffffffu, ib0 | ib1)) {
                    float4 q0 = s_q0[kk];
                    float4 q1 = s_q1[kk];
                    float4 q2 = s_q2[kk];
                    float dx  = px  - q2.x;
                    float dy0 = py0 - q2.y;
                    float dy1 = py1 - q2.y;
                    float dz  = pz  - q2.z;
                    // shared xz part + shared y-cross helper
                    float exz = fmaf(fmaf(q0.x, dx, q1.z * dz), dx, (q0.z * dz) * dz);
                    float hy  = fmaf(q1.x, dx, q1.y * dz);
                    float e0  = fmaf(fmaf(q0.y, dy0, hy), dy0, exz);
                    float e1  = fmaf(fmaf(q0.y, dy1, hy), dy1, exz);
                    float ww0, ww1;
                    asm("ex2.approx.ftz.f32 %0, %1;" : "=f"(ww0) : "f"(e0));
                    asm("ex2.approx.ftz.f32 %0, %1;" : "=f"(ww1) : "f"(e1));
                    w0 = ib0 ? ww0 : 0.0f;
                    w1 = ib1 ? ww1 : 0.0f;
                }
                wbuf[k * WROW + lane]      = __float2half_rn(w0);
                wbuf[k * WROW + lane + 32] = __float2half_rn(w1);
            }
            __syncwarp();

            // B fragments (sem cols 0-7, 8-15) for this k16
            unsigned b0, b1, b2, b3;
            unsigned baddr = semT_base + (unsigned)((kb + (lane & 15)) * 32 + ((lane >> 4) << 4));
            ldsm_x4_trans(baddr, b0, b1, b2, b3);

            // A fragments from private W (k-major, 144B rows), 4 m16 tiles
            const int krow = (lane & 7) + ((lane >> 4) << 3);
            const int mcol = ((lane >> 3) & 1) * 8;
#pragma unroll
            for (int mt = 0; mt < 4; mt++) {
                unsigned a0, a1, a2, a3;
                unsigned aaddr = wbase + (unsigned)(krow * (WROW * 2) + (mt * 16 + mcol) * 2);
                ldsm_x4_trans(aaddr, a0, a1, a2, a3);
                mma16816(acc[mt][0], a0, a1, a2, a3, b0, b1);
                mma16816(acc[mt][1], a0, a1, a2, a3, b2, b3);
            }
            __syncwarp();   // before next c overwrites wbuf
        }
        __syncthreads();    // before restaging
    }

    // Epilogue: write this parity's partial sums
    {
        float* po = (float*)g_part4[ks];
        const int gr  = lane >> 2;
        const int cc2 = (lane & 3) * 2;
#pragma unroll
        for (int mt = 0; mt < 4; mt++) {
#pragma unroll
            for (int h = 0; h < 2; h++) {
                int r = (wid << 6) + mt * 16 + gr + h * 8;
                int x = tlo_x + (r >> 6);
                int y = tlo_y + ((r >> 3) & 7);
                int z = tlo_z + (r & 7);
                if (y < WW && z < DDZ) {
                    float* o = po + ((x * WW + y) * DDZ + z) * NC;
                    o[cc2]     = acc[mt][0][2 * h + 0];
                    o[cc2 + 1] = acc[mt][0][2 * h + 1];
                    int cB = 8 + cc2;
                    if (cB < NC)     o[cB]     = acc[mt][1][2 * h + 0];
                    if (cB + 1 < NC) o[cB + 1] = acc[mt][1][2 * h + 1];
                }
            }
        }
    }
}

__global__ __launch_bounds__(256)
void merge_kernel(float4* __restrict__ out)
{
    int i = blockIdx.x * blockDim.x + threadIdx.x;
    if (i < NVOX * NC / 4) {
        float4 a = g_part4[0][i];
        float4 b = g_part4[1][i];
        out[i] = make_float4(a.x + b.x, a.y + b.y, a.z + b.z, a.w + b.w);
    }
}

extern "C" void kernel_launch(void* const* d_in, const int* in_sizes, int n_in,
                              void* d_out, int out_size)
{
    const float* pts      = (const float*)d_in[0];   // [1,129600,3]
    const float* means3D  = (const float*)d_in[1];   // [1,2048,3]
    const float* opac     = (const float*)d_in[2];   // [1,2048]
    const float* sem      = (const float*)d_in[3];   // [1,2048,13]
    const float* scales   = (const float*)d_in[4];   // [1,2048,3]
    const float* cov3D    = (const float*)d_in[5];   // [1,2048,3,3]
    const float* origin   = (const float*)d_in[6];   // [3]
    float* out = (float*)d_out;                      // [129600,13] f32

    precompute_kernel<<<(NP + 255) / 256, 256>>>(means3D, opac, sem, scales, cov3D, origin);

    dim3 grid(HH / TXC, (WW + TYC - 1) / TYC, 2 * ((DDZ + TZC - 1) / TZC));  // 15, 8, 10
    aggregate_kernel<<<grid, TPB>>>(pts, origin);

    int n4 = NVOX * NC / 4;
    merge_kernel<<<(n4 + 255) / 256, 256>>>((float4*)out);
}